// round 2
// baseline (speedup 1.0000x reference)
#include <cuda_runtime.h>

#define NN 50000
#define NE 200000
#define H  128
#define HV4 32   // H/4

// Scratch (device globals: allocation-free per harness rules)
__device__ float g_node_h[NN * H];   // 25.6 MB
__device__ float g_edge_h[NE * H];   // 102.4 MB
__device__ float g_agg[NN * H];      // 25.6 MB

__device__ __forceinline__ void fma4(float4& acc, const float4& wv, float s) {
    acc.x += wv.x * s;
    acc.y += wv.y * s;
    acc.z += wv.z * s;
    acc.w += wv.w * s;
}

__global__ void zero_kernel(float4* __restrict__ p, int n4) {
    int i = blockIdx.x * blockDim.x + threadIdx.x;
    if (i < n4) p[i] = make_float4(0.f, 0.f, 0.f, 0.f);
}

// ---------------------------------------------------------------------------
// Generic embed GEMM: out[rows,H] = X[rows,K] @ W[K,H] + b
// Block = 256 threads (8 warps). Each chunk = 32 rows; each warp owns 4 rows,
// each lane computes 4 columns (float4). W staged in dynamic smem.
// ---------------------------------------------------------------------------
template<int K>
__global__ void embed_kernel(const float* __restrict__ X,
                             const float* __restrict__ W,
                             const float* __restrict__ b,
                             float* __restrict__ out, int rows)
{
    extern __shared__ float sm[];
    float* Wsh  = sm;            // K*H floats
    float* xbuf = sm + K * H;    // 32*K floats

    const int tid  = threadIdx.x;
    const int lane = tid & 31;
    const int wid  = tid >> 5;

    for (int i = tid; i < K * H / 4; i += blockDim.x)
        ((float4*)Wsh)[i] = ((const float4*)W)[i];
    const float4 bias = ((const float4*)b)[lane];

    for (int r0 = blockIdx.x * 32; r0 < rows; r0 += gridDim.x * 32) {
        __syncthreads();
        const int nrows = min(32, rows - r0);
        for (int i = tid; i < nrows * (K / 4); i += blockDim.x)
            ((float4*)xbuf)[i] = ((const float4*)(X + (size_t)r0 * K))[i];
        __syncthreads();

        const int rbase = wid * 4;
        if (rbase < nrows) {   // nrows is always a multiple of 4 for these shapes
            float4 acc0 = make_float4(0.f, 0.f, 0.f, 0.f);
            float4 acc1 = acc0, acc2 = acc0, acc3 = acc0;
            const float* xr0 = xbuf + (rbase + 0) * K;
            const float* xr1 = xbuf + (rbase + 1) * K;
            const float* xr2 = xbuf + (rbase + 2) * K;
            const float* xr3 = xbuf + (rbase + 3) * K;
            #pragma unroll 4
            for (int k = 0; k < K; k++) {
                float4 wv = ((float4*)Wsh)[k * HV4 + lane];
                fma4(acc0, wv, xr0[k]);
                fma4(acc1, wv, xr1[k]);
                fma4(acc2, wv, xr2[k]);
                fma4(acc3, wv, xr3[k]);
            }
            float4 accs[4] = {acc0, acc1, acc2, acc3};
            #pragma unroll
            for (int rr = 0; rr < 4; rr++) {
                float4 o;
                o.x = accs[rr].x + bias.x;
                o.y = accs[rr].y + bias.y;
                o.z = accs[rr].z + bias.z;
                o.w = accs[rr].w + bias.w;
                ((float4*)out)[(size_t)(r0 + rbase + rr) * HV4 + lane] = o;
            }
        }
    }
}

// ---------------------------------------------------------------------------
// Per-edge: gate = sigmoid([src_f,dst_f,edge_h] . W_top + b_top)
// messages = src_f * gate + edge_h, scatter-add into agg[dst].
// One warp per edge; float4 per lane.
// ---------------------------------------------------------------------------
__global__ void edge_kernel(const float* __restrict__ node_h,
                            const float* __restrict__ edge_h,
                            const int* __restrict__ src,
                            const int* __restrict__ dst,
                            const float* __restrict__ W_top,
                            const float* __restrict__ b_top,
                            float* __restrict__ agg,
                            float* __restrict__ ew)
{
    __shared__ float wsh[3 * H];
    const int tid  = threadIdx.x;
    const int lane = tid & 31;
    const int wid  = tid >> 5;
    for (int i = tid; i < 3 * H; i += blockDim.x) wsh[i] = W_top[i];
    __syncthreads();

    const int e = blockIdx.x * 8 + wid;
    if (e >= NE) return;

    const int s = src[e];
    const int d = dst[e];
    float4 sf = ((const float4*)node_h)[(size_t)s * HV4 + lane];
    float4 df = ((const float4*)node_h)[(size_t)d * HV4 + lane];
    float4 ef = ((const float4*)edge_h)[(size_t)e * HV4 + lane];
    float4 ws = ((float4*)wsh)[lane];
    float4 wd = ((float4*)wsh)[32 + lane];
    float4 we = ((float4*)wsh)[64 + lane];

    float p = sf.x * ws.x + sf.y * ws.y + sf.z * ws.z + sf.w * ws.w
            + df.x * wd.x + df.y * wd.y + df.z * wd.z + df.w * wd.w
            + ef.x * we.x + ef.y * we.y + ef.z * we.z + ef.w * we.w;
    #pragma unroll
    for (int off = 16; off; off >>= 1)
        p += __shfl_xor_sync(0xffffffffu, p, off);

    const float w = 1.f / (1.f + __expf(-(p + b_top[0])));

    float* ap = agg + (size_t)d * H + lane * 4;
    atomicAdd(ap + 0, sf.x * w + ef.x);
    atomicAdd(ap + 1, sf.y * w + ef.y);
    atomicAdd(ap + 2, sf.z * w + ef.z);
    atomicAdd(ap + 3, sf.w * w + ef.w);

    if (lane == 0) ew[e] = w;
}

// ---------------------------------------------------------------------------
// GNN dense + residual + LayerNorm + ReLU, fused.
// updated = [node_h | agg] @ W[256,128] + b
// out = relu(LN(node_h + updated) * scale + bias)
// Same blocking as embed_kernel; each warp owns whole rows, so the LN
// reduction is warp-local (butterfly shuffles).
// ---------------------------------------------------------------------------
__global__ void gnn_kernel(const float* __restrict__ node_h,
                           const float* __restrict__ agg,
                           const float* __restrict__ W,     // [256,128]
                           const float* __restrict__ b,
                           const float* __restrict__ lns,
                           const float* __restrict__ lnb,
                           float* __restrict__ out, int rows)
{
    extern __shared__ float sm[];
    float* Wsh  = sm;              // 256*128 floats = 128 KB
    float* xbuf = sm + 256 * H;    // 32*256 floats = 32 KB

    const int tid  = threadIdx.x;
    const int lane = tid & 31;
    const int wid  = tid >> 5;

    for (int i = tid; i < 256 * H / 4; i += blockDim.x)
        ((float4*)Wsh)[i] = ((const float4*)W)[i];
    const float4 bias = ((const float4*)b)[lane];
    const float4 sc   = ((const float4*)lns)[lane];
    const float4 bi   = ((const float4*)lnb)[lane];

    for (int r0 = blockIdx.x * 32; r0 < rows; r0 += gridDim.x * 32) {
        __syncthreads();
        const int nrows = min(32, rows - r0);
        for (int i = tid; i < nrows * HV4; i += blockDim.x) {
            const int r = i >> 5, c = i & 31;
            ((float4*)(xbuf + r * 256))[c]     = ((const float4*)node_h)[(size_t)(r0 + r) * HV4 + c];
            ((float4*)(xbuf + r * 256 + H))[c] = ((const float4*)agg)[(size_t)(r0 + r) * HV4 + c];
        }
        __syncthreads();

        const int rbase = wid * 4;
        if (rbase < nrows) {
            float4 acc0 = make_float4(0.f, 0.f, 0.f, 0.f);
            float4 acc1 = acc0, acc2 = acc0, acc3 = acc0;
            const float* xr0 = xbuf + (rbase + 0) * 256;
            const float* xr1 = xbuf + (rbase + 1) * 256;
            const float* xr2 = xbuf + (rbase + 2) * 256;
            const float* xr3 = xbuf + (rbase + 3) * 256;
            #pragma unroll 4
            for (int k = 0; k < 256; k++) {
                float4 wv = ((float4*)Wsh)[k * HV4 + lane];
                fma4(acc0, wv, xr0[k]);
                fma4(acc1, wv, xr1[k]);
                fma4(acc2, wv, xr2[k]);
                fma4(acc3, wv, xr3[k]);
            }
            float4 accs[4] = {acc0, acc1, acc2, acc3};
            #pragma unroll
            for (int rr = 0; rr < 4; rr++) {
                float4 res = ((float4*)(xbuf + (rbase + rr) * 256))[lane];
                float4 v;
                v.x = res.x + accs[rr].x + bias.x;
                v.y = res.y + accs[rr].y + bias.y;
                v.z = res.z + accs[rr].z + bias.z;
                v.w = res.w + accs[rr].w + bias.w;
                float s  = v.x + v.y + v.z + v.w;
                float ss = v.x * v.x + v.y * v.y + v.z * v.z + v.w * v.w;
                #pragma unroll
                for (int off = 16; off; off >>= 1) {
                    s  += __shfl_xor_sync(0xffffffffu, s, off);
                    ss += __shfl_xor_sync(0xffffffffu, ss, off);
                }
                const float mean = s * (1.f / 128.f);
                const float var  = ss * (1.f / 128.f) - mean * mean;
                const float rstd = rsqrtf(var + 1e-6f);
                float4 o;
                o.x = fmaxf((v.x - mean) * rstd * sc.x + bi.x, 0.f);
                o.y = fmaxf((v.y - mean) * rstd * sc.y + bi.y, 0.f);
                o.z = fmaxf((v.z - mean) * rstd * sc.z + bi.z, 0.f);
                o.w = fmaxf((v.w - mean) * rstd * sc.w + bi.w, 0.f);
                ((float4*)out)[(size_t)(r0 + rbase + rr) * HV4 + lane] = o;
            }
        }
    }
}

extern "C" void kernel_launch(void* const* d_in, const int* in_sizes, int n_in,
                              void* d_out, int out_size)
{
    const float* node_features = (const float*)d_in[0];
    const float* edge_features = (const float*)d_in[1];
    const int*   edge_indices  = (const int*)d_in[2];
    const float* W_node   = (const float*)d_in[3];
    const float* b_node   = (const float*)d_in[4];
    const float* W_edge   = (const float*)d_in[5];
    const float* b_edge   = (const float*)d_in[6];
    const float* W_gnn    = (const float*)d_in[7];
    const float* b_gnn    = (const float*)d_in[8];
    const float* W_top    = (const float*)d_in[9];
    const float* b_top    = (const float*)d_in[10];
    const float* ln_scale = (const float*)d_in[11];
    const float* ln_bias  = (const float*)d_in[12];

    float *node_h, *edge_h, *agg;
    cudaGetSymbolAddress((void**)&node_h, g_node_h);
    cudaGetSymbolAddress((void**)&edge_h, g_edge_h);
    cudaGetSymbolAddress((void**)&agg,    g_agg);

    float* out_node = (float*)d_out;                       // [NN, H]
    float* out_ew   = (float*)d_out + (size_t)NN * H;      // [NE]

    const int smem_embed128 = (128 * H + 32 * 128) * 4;    // 80 KB
    const int smem_embed64  = (64 * H + 32 * 64) * 4;      // 40 KB
    const int smem_gnn      = (256 * H + 32 * 256) * 4;    // 160 KB
    cudaFuncSetAttribute(embed_kernel<128>, cudaFuncAttributeMaxDynamicSharedMemorySize, smem_embed128);
    cudaFuncSetAttribute(embed_kernel<64>,  cudaFuncAttributeMaxDynamicSharedMemorySize, smem_embed64);
    cudaFuncSetAttribute(gnn_kernel,        cudaFuncAttributeMaxDynamicSharedMemorySize, smem_gnn);

    embed_kernel<128><<<512, 256, smem_embed128>>>(node_features, W_node, b_node, node_h, NN);
    embed_kernel<64> <<<512, 256, smem_embed64 >>>(edge_features, W_edge, b_edge, edge_h, NE);

    const int* srcp = edge_indices;
    const int* dstp = edge_indices + NE;

    for (int i = 0; i < 3; i++) {
        zero_kernel<<<NN * H / 4 / 256, 256>>>((float4*)agg, NN * H / 4);
        edge_kernel<<<NE / 8, 256>>>(node_h, edge_h, srcp, dstp, W_top, b_top, agg, out_ew);
        gnn_kernel<<<296, 256, smem_gnn>>>(node_h, agg,
                                           W_gnn + (size_t)i * 256 * H,
                                           b_gnn + i * H,
                                           ln_scale + i * H,
                                           ln_bias + i * H,
                                           (i == 2) ? out_node : node_h, NN);
    }
}

// round 3
// speedup vs baseline: 1.1087x; 1.1087x over previous
#include <cuda_runtime.h>

#define NN 50000
#define NE 200000
#define H  128
#define HV4 32   // H/4

// Scratch (device globals: allocation-free per harness rules)
__device__ float g_node_h[NN * H];        // 25.6 MB
__device__ float g_agg[NN * H];           // 25.6 MB
__device__ float g_agg_base[NN * H];      // 25.6 MB  Σ edge_h per dst (via factorization)
__device__ float g_escratch[NN * 65];     // eaggF [NN,64] + deg [NN]
__device__ float g_edot[NE];              // folded edge-constant gate logit
__device__ float g_wcombo[65];            // W_edge @ w_top_e (64) + folded bias

__device__ __forceinline__ void fma4(float4& acc, const float4& wv, float s) {
    acc.x += wv.x * s;
    acc.y += wv.y * s;
    acc.z += wv.z * s;
    acc.w += wv.w * s;
}

__global__ void zero_kernel(float4* __restrict__ p, int n4) {
    int i = blockIdx.x * blockDim.x + threadIdx.x;
    if (i < n4) p[i] = make_float4(0.f, 0.f, 0.f, 0.f);
}

// ---------------------------------------------------------------------------
// Tiny precompute: wcombo[k] = sum_h W_edge[k,h] * W_top[2H+h]
//                  wcombo[64] = b_top + sum_h b_edge[h] * W_top[2H+h]
// ---------------------------------------------------------------------------
__global__ void combo_kernel(const float* __restrict__ W_edge,
                             const float* __restrict__ W_top,
                             const float* __restrict__ b_edge,
                             const float* __restrict__ b_top,
                             float* __restrict__ wcombo)
{
    const int k = threadIdx.x;   // 64 threads
    float s = 0.f;
    for (int h = 0; h < H; h++) s += W_edge[k * H + h] * W_top[2 * H + h];
    wcombo[k] = s;
    if (k == 0) {
        float b = b_top[0];
        for (int h = 0; h < H; h++) b += b_edge[h] * W_top[2 * H + h];
        wcombo[64] = b;
    }
}

// ---------------------------------------------------------------------------
// Per-edge precompute (once): e_dot[e] = ef[e] . wcombo + bias_const
// and scatter-add raw edge_features into eaggF[dst], deg[dst] += 1.
// One warp per edge, float2 per lane (64 features).
// ---------------------------------------------------------------------------
__global__ void edge_pre_kernel(const float* __restrict__ ef,
                                const int* __restrict__ dst,
                                const float* __restrict__ wcombo,
                                float* __restrict__ eaggF,
                                float* __restrict__ deg,
                                float* __restrict__ edot)
{
    __shared__ float wsh[65];
    const int tid  = threadIdx.x;
    const int lane = tid & 31;
    const int wid  = tid >> 5;
    if (tid < 65) wsh[tid] = wcombo[tid];
    __syncthreads();

    const int e = blockIdx.x * 8 + wid;
    const int d = dst[e];
    float2 v = ((const float2*)ef)[(size_t)e * 32 + lane];
    float p = v.x * wsh[lane * 2] + v.y * wsh[lane * 2 + 1];
    #pragma unroll
    for (int off = 16; off; off >>= 1)
        p += __shfl_xor_sync(0xffffffffu, p, off);
    if (lane == 0) {
        edot[e] = p + wsh[64];
        atomicAdd(deg + d, 1.f);
    }
    float* ap = eaggF + (size_t)d * 64 + lane * 2;
    atomicAdd(ap + 0, v.x);
    atomicAdd(ap + 1, v.y);
}

// ---------------------------------------------------------------------------
// Embed GEMM: out[rows,H] = X[rows,K] @ W[K,H] + scale*b
// scale = deg[row] when deg != nullptr, else 1. 256 thr, 32-row chunks.
// ---------------------------------------------------------------------------
template<int K>
__global__ void embed_kernel(const float* __restrict__ X,
                             const float* __restrict__ W,
                             const float* __restrict__ b,
                             const float* __restrict__ deg,
                             float* __restrict__ out, int rows)
{
    extern __shared__ float sm[];
    float* Wsh  = sm;            // K*H floats
    float* xbuf = sm + K * H;    // 32*K floats

    const int tid  = threadIdx.x;
    const int lane = tid & 31;
    const int wid  = tid >> 5;

    for (int i = tid; i < K * H / 4; i += blockDim.x)
        ((float4*)Wsh)[i] = ((const float4*)W)[i];
    const float4 bias = ((const float4*)b)[lane];

    for (int r0 = blockIdx.x * 32; r0 < rows; r0 += gridDim.x * 32) {
        __syncthreads();
        const int nrows = min(32, rows - r0);
        for (int i = tid; i < nrows * (K / 4); i += blockDim.x)
            ((float4*)xbuf)[i] = ((const float4*)(X + (size_t)r0 * K))[i];
        __syncthreads();

        const int rbase = wid * 4;
        if (rbase < nrows) {
            float4 acc0 = make_float4(0.f, 0.f, 0.f, 0.f);
            float4 acc1 = acc0, acc2 = acc0, acc3 = acc0;
            const float* xr0 = xbuf + (rbase + 0) * K;
            const float* xr1 = xbuf + (rbase + 1) * K;
            const float* xr2 = xbuf + (rbase + 2) * K;
            const float* xr3 = xbuf + (rbase + 3) * K;
            #pragma unroll 4
            for (int k = 0; k < K; k++) {
                float4 wv = ((float4*)Wsh)[k * HV4 + lane];
                fma4(acc0, wv, xr0[k]);
                fma4(acc1, wv, xr1[k]);
                fma4(acc2, wv, xr2[k]);
                fma4(acc3, wv, xr3[k]);
            }
            float4 accs[4] = {acc0, acc1, acc2, acc3};
            #pragma unroll
            for (int rr = 0; rr < 4; rr++) {
                const float sc = deg ? deg[r0 + rbase + rr] : 1.f;
                float4 o;
                o.x = accs[rr].x + sc * bias.x;
                o.y = accs[rr].y + sc * bias.y;
                o.z = accs[rr].z + sc * bias.z;
                o.w = accs[rr].w + sc * bias.w;
                ((float4*)out)[(size_t)(r0 + rbase + rr) * HV4 + lane] = o;
            }
        }
    }
}

// ---------------------------------------------------------------------------
// Slim per-layer edge kernel: gate from node gathers + precomputed e_dot,
// RED src_f * w into agg (pre-seeded with agg_base).
// ---------------------------------------------------------------------------
template<bool WRITE_EW>
__global__ void edge_slim_kernel(const float* __restrict__ node_h,
                                 const int* __restrict__ src,
                                 const int* __restrict__ dst,
                                 const float* __restrict__ W_top,
                                 const float* __restrict__ edot,
                                 float* __restrict__ agg,
                                 float* __restrict__ ew)
{
    __shared__ float wsh[2 * H];
    const int tid  = threadIdx.x;
    const int lane = tid & 31;
    const int wid  = tid >> 5;
    if (tid < 2 * H) wsh[tid] = W_top[tid];
    __syncthreads();

    const int e = blockIdx.x * 8 + wid;
    const int s = src[e];
    const int d = dst[e];
    float4 sf = ((const float4*)node_h)[(size_t)s * HV4 + lane];
    float4 df = ((const float4*)node_h)[(size_t)d * HV4 + lane];
    float4 ws = ((float4*)wsh)[lane];
    float4 wd = ((float4*)wsh)[32 + lane];

    float p = sf.x * ws.x + sf.y * ws.y + sf.z * ws.z + sf.w * ws.w
            + df.x * wd.x + df.y * wd.y + df.z * wd.z + df.w * wd.w;
    #pragma unroll
    for (int off = 16; off; off >>= 1)
        p += __shfl_xor_sync(0xffffffffu, p, off);

    const float w = 1.f / (1.f + __expf(-(p + edot[e])));

    float* ap = agg + (size_t)d * H + lane * 4;
    atomicAdd(ap + 0, sf.x * w);
    atomicAdd(ap + 1, sf.y * w);
    atomicAdd(ap + 2, sf.z * w);
    atomicAdd(ap + 3, sf.w * w);

    if (WRITE_EW && lane == 0) ew[e] = w;
}

// ---------------------------------------------------------------------------
// GNN dense + residual + LayerNorm + ReLU, fused. 512 threads, 64-row chunks.
// ---------------------------------------------------------------------------
__global__ void gnn_kernel(const float* __restrict__ node_h,
                           const float* __restrict__ agg,
                           const float* __restrict__ W,     // [256,128]
                           const float* __restrict__ b,
                           const float* __restrict__ lns,
                           const float* __restrict__ lnb,
                           float* __restrict__ out, int rows)
{
    extern __shared__ float sm[];
    float* Wsh  = sm;              // 256*128 floats = 128 KB
    float* xbuf = sm + 256 * H;    // 64*256 floats = 64 KB

    const int tid  = threadIdx.x;
    const int lane = tid & 31;
    const int wid  = tid >> 5;

    for (int i = tid; i < 256 * H / 4; i += blockDim.x)
        ((float4*)Wsh)[i] = ((const float4*)W)[i];
    const float4 bias = ((const float4*)b)[lane];
    const float4 sc   = ((const float4*)lns)[lane];
    const float4 bi   = ((const float4*)lnb)[lane];

    for (int r0 = blockIdx.x * 64; r0 < rows; r0 += gridDim.x * 64) {
        __syncthreads();
        const int nrows = min(64, rows - r0);
        for (int i = tid; i < nrows * HV4; i += blockDim.x) {
            const int r = i >> 5, c = i & 31;
            ((float4*)(xbuf + r * 256))[c]     = ((const float4*)node_h)[(size_t)(r0 + r) * HV4 + c];
            ((float4*)(xbuf + r * 256 + H))[c] = ((const float4*)agg)[(size_t)(r0 + r) * HV4 + c];
        }
        __syncthreads();

        const int rbase = wid * 4;
        if (rbase < nrows) {
            float4 acc0 = make_float4(0.f, 0.f, 0.f, 0.f);
            float4 acc1 = acc0, acc2 = acc0, acc3 = acc0;
            const float* xr0 = xbuf + (rbase + 0) * 256;
            const float* xr1 = xbuf + (rbase + 1) * 256;
            const float* xr2 = xbuf + (rbase + 2) * 256;
            const float* xr3 = xbuf + (rbase + 3) * 256;
            #pragma unroll 4
            for (int k = 0; k < 256; k++) {
                float4 wv = ((float4*)Wsh)[k * HV4 + lane];
                fma4(acc0, wv, xr0[k]);
                fma4(acc1, wv, xr1[k]);
                fma4(acc2, wv, xr2[k]);
                fma4(acc3, wv, xr3[k]);
            }
            float4 accs[4] = {acc0, acc1, acc2, acc3};
            #pragma unroll
            for (int rr = 0; rr < 4; rr++) {
                float4 res = ((float4*)(xbuf + (rbase + rr) * 256))[lane];
                float4 v;
                v.x = res.x + accs[rr].x + bias.x;
                v.y = res.y + accs[rr].y + bias.y;
                v.z = res.z + accs[rr].z + bias.z;
                v.w = res.w + accs[rr].w + bias.w;
                float s  = v.x + v.y + v.z + v.w;
                float ss = v.x * v.x + v.y * v.y + v.z * v.z + v.w * v.w;
                #pragma unroll
                for (int off = 16; off; off >>= 1) {
                    s  += __shfl_xor_sync(0xffffffffu, s, off);
                    ss += __shfl_xor_sync(0xffffffffu, ss, off);
                }
                const float mean = s * (1.f / 128.f);
                const float var  = ss * (1.f / 128.f) - mean * mean;
                const float rstd = rsqrtf(var + 1e-6f);
                float4 o;
                o.x = fmaxf((v.x - mean) * rstd * sc.x + bi.x, 0.f);
                o.y = fmaxf((v.y - mean) * rstd * sc.y + bi.y, 0.f);
                o.z = fmaxf((v.z - mean) * rstd * sc.z + bi.z, 0.f);
                o.w = fmaxf((v.w - mean) * rstd * sc.w + bi.w, 0.f);
                ((float4*)out)[(size_t)(r0 + rbase + rr) * HV4 + lane] = o;
            }
        }
    }
}

extern "C" void kernel_launch(void* const* d_in, const int* in_sizes, int n_in,
                              void* d_out, int out_size)
{
    const float* node_features = (const float*)d_in[0];
    const float* edge_features = (const float*)d_in[1];
    const int*   edge_indices  = (const int*)d_in[2];
    const float* W_node   = (const float*)d_in[3];
    const float* b_node   = (const float*)d_in[4];
    const float* W_edge   = (const float*)d_in[5];
    const float* b_edge   = (const float*)d_in[6];
    const float* W_gnn    = (const float*)d_in[7];
    const float* b_gnn    = (const float*)d_in[8];
    const float* W_top    = (const float*)d_in[9];
    const float* b_top    = (const float*)d_in[10];
    const float* ln_scale = (const float*)d_in[11];
    const float* ln_bias  = (const float*)d_in[12];

    float *node_h, *agg, *agg_base, *escratch, *edot, *wcombo;
    cudaGetSymbolAddress((void**)&node_h,   g_node_h);
    cudaGetSymbolAddress((void**)&agg,      g_agg);
    cudaGetSymbolAddress((void**)&agg_base, g_agg_base);
    cudaGetSymbolAddress((void**)&escratch, g_escratch);
    cudaGetSymbolAddress((void**)&edot,     g_edot);
    cudaGetSymbolAddress((void**)&wcombo,   g_wcombo);
    float* eaggF = escratch;            // [NN, 64]
    float* deg   = escratch + NN * 64;  // [NN]

    float* out_node = (float*)d_out;                       // [NN, H]
    float* out_ew   = (float*)d_out + (size_t)NN * H;      // [NE]

    const int* srcp = edge_indices;
    const int* dstp = edge_indices + NE;

    const int smem_embed128 = (128 * H + 32 * 128) * 4;    // 80 KB
    const int smem_embed64  = (64 * H + 32 * 64) * 4;      // 40 KB
    const int smem_gnn      = (256 * H + 64 * 256) * 4;    // 192 KB
    cudaFuncSetAttribute(embed_kernel<128>, cudaFuncAttributeMaxDynamicSharedMemorySize, smem_embed128);
    cudaFuncSetAttribute(embed_kernel<64>,  cudaFuncAttributeMaxDynamicSharedMemorySize, smem_embed64);
    cudaFuncSetAttribute(gnn_kernel,        cudaFuncAttributeMaxDynamicSharedMemorySize, smem_gnn);

    // --- one-time precompute (per call) ---
    combo_kernel<<<1, 64>>>(W_edge, W_top, b_edge, b_top, wcombo);
    zero_kernel<<<(NN * 65 / 4 + 255) / 256, 256>>>((float4*)escratch, NN * 65 / 4);
    edge_pre_kernel<<<NE / 8, 256>>>(edge_features, dstp, wcombo, eaggF, deg, edot);
    embed_kernel<64><<<512, 256, smem_embed64>>>(eaggF, W_edge, b_edge, deg, agg_base, NN);
    embed_kernel<128><<<512, 256, smem_embed128>>>(node_features, W_node, b_node, nullptr, node_h, NN);

    // --- layers ---
    for (int i = 0; i < 3; i++) {
        cudaMemcpyAsync(agg, agg_base, (size_t)NN * H * sizeof(float),
                        cudaMemcpyDeviceToDevice);
        if (i == 2)
            edge_slim_kernel<true><<<NE / 8, 256>>>(node_h, srcp, dstp, W_top, edot, agg, out_ew);
        else
            edge_slim_kernel<false><<<NE / 8, 256>>>(node_h, srcp, dstp, W_top, edot, agg, out_ew);
        gnn_kernel<<<148, 512, smem_gnn>>>(node_h, agg,
                                           W_gnn + (size_t)i * 256 * H,
                                           b_gnn + i * H,
                                           ln_scale + i * H,
                                           ln_bias + i * H,
                                           (i == 2) ? out_node : node_h, NN);
    }
}